// round 13
// baseline (speedup 1.0000x reference)
#include <cuda_runtime.h>
#include <cuda_bf16.h>
#include <math.h>
#include <stdint.h>

#define T_TOK 8192
#define D_DIM 2048
#define F_DIM 3584
#define E_NUM 8
#define N1 (2 * F_DIM)          // 7168
#define MT_MAX 136
#define MAX_ROWS (MT_MAX * 128)

#define W1E ((size_t)E_NUM * N1 * D_DIM)
#define W2E ((size_t)E_NUM * D_DIM * F_DIM)
#define XE  ((size_t)T_TOK * D_DIM)

// ---------------- scratch ----------------
__device__ float g_h[(size_t)MAX_ROWS * N1];     // gemm1 out; later reused as Y (gemm2 out)
__device__ float g_act[(size_t)MAX_ROWS * F_DIM];
__device__ float g_w1r[W1E];
__device__ float g_w2r[W2E];
__device__ float g_xr[XE];
__device__ int   g_tok[E_NUM * T_TOK];
__device__ int   g_slot[2 * T_TOK];              // per token: (e<<13)|p
__device__ float g_wt[2 * T_TOK];
__device__ int   g_cnt[E_NUM];
__device__ int   g_ts[E_NUM + 1];

// ---------------- helpers ----------------
__device__ __forceinline__ uint32_t smem_u32(const void* p) {
    uint32_t a;
    asm("{ .reg .u64 t; cvta.to.shared.u64 t, %1; cvt.u32.u64 %0, t; }" : "=r"(a) : "l"(p));
    return a;
}
__device__ __forceinline__ float tf32r(float v) {
    uint32_t r;
    asm("cvt.rna.tf32.f32 %0, %1;" : "=r"(r) : "f"(v));
    return __uint_as_float(r);
}
#define CP_ASYNC16(dst, src, sz) \
    asm volatile("cp.async.cg.shared.global [%0], [%1], 16, %2;" :: "r"(dst), "l"(src), "r"(sz) : "memory")
#define CP_COMMIT() asm volatile("cp.async.commit_group;" ::: "memory")
#define CP_WAIT(n)  asm volatile("cp.async.wait_group %0;" :: "n"(n) : "memory")

// padded + chunk-permuted row: stride 144B; 16B-chunk kc stored at (kc + 2*row)&7
#define RPB 144
#define TILE_T (128 * RPB)        // 18432 B (A or B tile: 128 rows x 32 K)
#define STAGE  (2 * TILE_T)       // 36864 B
#define NSTG   3
#define DSMEM_SZ (NSTG * STAGE + 1024)

__device__ __forceinline__ uint32_t taddr(uint32_t base, int row, int col) {
    int pc = ((col >> 2) + 2 * row) & 7;
    return base + row * RPB + pc * 16 + (col & 3) * 4;
}
__device__ __forceinline__ uint32_t lds_raw(uint32_t a) {
    uint32_t v;
    asm volatile("ld.shared.b32 %0, [%1];" : "=r"(v) : "r"(a));
    return v;
}
#define MMA_TF32(c, a, b0, b1)                                                      \
    asm volatile("mma.sync.aligned.m16n8k8.row.col.f32.tf32.tf32.f32 "              \
        "{%0,%1,%2,%3}, {%4,%5,%6,%7}, {%8,%9}, {%0,%1,%2,%3};"                     \
        : "+f"((c)[0]), "+f"((c)[1]), "+f"((c)[2]), "+f"((c)[3])                    \
        : "r"((a)[0]), "r"((a)[1]), "r"((a)[2]), "r"((a)[3]), "r"(b0), "r"(b1))

// ---------------- pre-pass ----------------
__global__ void cvt_all_kernel(const float* __restrict__ x,
                               const float* __restrict__ wv1,
                               const float* __restrict__ w2) {
    if (blockIdx.x == 0 && threadIdx.x < E_NUM) g_cnt[threadIdx.x] = 0;
    const size_t W1Q = W1E / 4, W2Q = W2E / 4, XQ = XE / 4;
    size_t i = (size_t)blockIdx.x * blockDim.x + threadIdx.x;
    const float4* src;
    float4* dst;
    if (i < W1Q) {
        src = (const float4*)wv1 + i;             dst = (float4*)g_w1r + i;
    } else if (i < W1Q + W2Q) {
        src = (const float4*)w2 + (i - W1Q);      dst = (float4*)g_w2r + (i - W1Q);
    } else if (i < W1Q + W2Q + XQ) {
        src = (const float4*)x + (i - W1Q - W2Q); dst = (float4*)g_xr + (i - W1Q - W2Q);
    } else return;
    float4 v = *src;
    v.x = tf32r(v.x); v.y = tf32r(v.y); v.z = tf32r(v.z); v.w = tf32r(v.w);
    *dst = v;
}

// ---------------- gating ----------------
__global__ void gate_kernel(const float* __restrict__ x, const float* __restrict__ gw) {
    int warp = (blockIdx.x * blockDim.x + threadIdx.x) >> 5;
    int lane = threadIdx.x & 31;
    if (warp >= T_TOK) return;
    const float* xr = x + (size_t)warp * D_DIM;
    float acc[E_NUM];
#pragma unroll
    for (int e = 0; e < E_NUM; e++) acc[e] = 0.f;
    for (int d = lane; d < D_DIM; d += 32) {
        float xv = xr[d];
#pragma unroll
        for (int e = 0; e < E_NUM; e++) acc[e] += xv * gw[e * D_DIM + d];
    }
#pragma unroll
    for (int e = 0; e < E_NUM; e++)
#pragma unroll
        for (int o = 16; o > 0; o >>= 1) acc[e] += __shfl_xor_sync(0xFFFFFFFFu, acc[e], o);
    if (lane == 0) {
        int i1 = 0; float l1 = acc[0];
#pragma unroll
        for (int e = 1; e < E_NUM; e++) if (acc[e] > l1) { l1 = acc[e]; i1 = e; }
        int i2 = -1; float l2 = -3.4e38f;
#pragma unroll
        for (int e = 0; e < E_NUM; e++) if (e != i1 && acc[e] > l2) { l2 = acc[e]; i2 = e; }
        float w1 = 1.f / (1.f + expf(l2 - l1));
        float w2 = 1.f - w1;
        int p1 = atomicAdd(&g_cnt[i1], 1);
        g_tok[i1 * T_TOK + p1] = warp;
        g_slot[2 * warp] = (i1 << 13) | p1; g_wt[2 * warp] = w1;
        int p2 = atomicAdd(&g_cnt[i2], 1);
        g_tok[i2 * T_TOK + p2] = warp;
        g_slot[2 * warp + 1] = (i2 << 13) | p2; g_wt[2 * warp + 1] = w2;
    }
}

__global__ void offs_kernel() {
    int t = 0;
    for (int e = 0; e < E_NUM; e++) { g_ts[e] = t; t += (g_cnt[e] + 127) >> 7; }
    g_ts[E_NUM] = t;
}

// flat silu: one float4 per thread over all padded rows (garbage rows are
// row-isolated and never stored downstream: gemm2 epilogue guards on s_tok).
__global__ void silu_kernel() {
    const int F4 = F_DIM / 4;
    int idx = blockIdx.x * blockDim.x + threadIdx.x;
    int row = idx / F4;
    if (row >= g_ts[E_NUM] * 128) return;
    int c4 = idx % F4;
    const float4* gp = (const float4*)(g_h + (size_t)row * N1) + c4;
    float4 g = gp[0];
    float4 u = gp[F_DIM / 4];
    float4 o;
    o.x = tf32r((g.x / (1.f + expf(-g.x))) * u.x);
    o.y = tf32r((g.y / (1.f + expf(-g.y))) * u.y);
    o.z = tf32r((g.z / (1.f + expf(-g.z))) * u.z);
    o.w = tf32r((g.w / (1.f + expf(-g.w))) * u.w);
    ((float4*)(g_act + (size_t)row * F_DIM))[c4] = o;
}

// final: out[t] = w1*Y[r1] + w2*Y[r2]
__global__ void combine_kernel(float* __restrict__ out) {
    const int C4 = D_DIM / 4;
    int idx = blockIdx.x * blockDim.x + threadIdx.x;
    if (idx >= T_TOK * C4) return;
    int t = idx / C4, c = idx % C4;
    int s1 = g_slot[2 * t], s2 = g_slot[2 * t + 1];
    float w1 = g_wt[2 * t], w2 = g_wt[2 * t + 1];
    int r1 = g_ts[s1 >> 13] * 128 + (s1 & 8191);
    int r2 = g_ts[s2 >> 13] * 128 + (s2 & 8191);
    float4 y1 = *((const float4*)g_h + (size_t)r1 * C4 + c);
    float4 y2 = *((const float4*)g_h + (size_t)r2 * C4 + c);
    float4 o;
    o.x = w1 * y1.x + w2 * y2.x;
    o.y = w1 * y1.y + w2 * y2.y;
    o.z = w1 * y1.z + w2 * y2.z;
    o.w = w1 * y1.w + w2 * y2.w;
    ((float4*)out)[idx] = o;
}

// ---------------- TF32 GEMM: CTA 128M x 128N, 4 warps (64x64), 3-stage, 2 CTA/SM ----------------
// ks-level register double-buffering + ks0 peel (cp.async issue after ks0 MMAs).
// MODE 0: A = g_xr gathered, W = g_w1r -> g_h[.,N1]       (K=2048, N=7168)
// MODE 1: A = g_act,         W = g_w2r -> Y=g_h[.,D_DIM]  (K=3584, N=2048)
template <int KTOT, int MODE>
__device__ __forceinline__ void load_stage(uint32_t Ab, uint32_t Bb,
                                           const float* __restrict__ W,
                                           const int* s_tok, int mt, int k0, int tid) {
#pragma unroll
    for (int i = 0; i < 16; i++) {
        int id = tid + 128 * i;
        if (id < 1024) {                      // A: 128 rows x 8 chunks
            int r = id >> 3, kc = id & 7;
            int pc = (kc + 2 * r) & 7;
            uint32_t ad = Ab + r * RPB + pc * 16;
            if (MODE == 0) {
                int tok = s_tok[r];
                const float* src = g_xr + (size_t)(tok < 0 ? 0 : tok) * KTOT + k0 + kc * 4;
                int sz = (tok >= 0) ? 16 : 0;
                CP_ASYNC16(ad, src, sz);
            } else {
                const float* src = g_act + (size_t)(mt * 128 + r) * KTOT + k0 + kc * 4;
                CP_ASYNC16(ad, src, 16);
            }
        } else {                              // B: 128 rows x 8 chunks
            int ib = id - 1024;
            int r = ib >> 3, kc = ib & 7;
            int pc = (kc + 2 * r) & 7;
            uint32_t bd = Bb + r * RPB + pc * 16;
            const float* bs = W + (size_t)r * KTOT + k0 + kc * 4;
            CP_ASYNC16(bd, bs, 16);
        }
    }
}

__device__ __forceinline__ void load_frags(uint32_t At, uint32_t Bt, int kb,
                                           int m0w, int n0w, int grp, int qid,
                                           uint32_t a[4][4], uint32_t b[8][2]) {
#pragma unroll
    for (int mf = 0; mf < 4; mf++) {
        int row = m0w + mf * 16 + grp;
        a[mf][0] = lds_raw(taddr(At, row,     kb + qid));
        a[mf][1] = lds_raw(taddr(At, row + 8, kb + qid));
        a[mf][2] = lds_raw(taddr(At, row,     kb + qid + 4));
        a[mf][3] = lds_raw(taddr(At, row + 8, kb + qid + 4));
    }
#pragma unroll
    for (int nb = 0; nb < 8; nb++) {
        int n = n0w + nb * 8 + grp;
        b[nb][0] = lds_raw(taddr(Bt, n, kb + qid));
        b[nb][1] = lds_raw(taddr(Bt, n, kb + qid + 4));
    }
}

template <int KTOT, int MODE>
__global__ void __launch_bounds__(128, 2) moe_gemm_tf32(float* __restrict__ Outp) {
    const int mt = blockIdx.y;
    int ts[E_NUM + 1];
#pragma unroll
    for (int i = 0; i <= E_NUM; i++) ts[i] = g_ts[i];
    if (mt >= ts[E_NUM]) return;
    int e = 0;
#pragma unroll
    for (int i = 0; i < E_NUM; i++) if (mt >= ts[i + 1]) e = i + 1;
    const int cnt = g_cnt[e];
    const int mloc0 = (mt - ts[e]) * 128;
    const int n0 = blockIdx.x * 128;
    const int NTOT = gridDim.x * 128;
    const float* __restrict__ Wbase = (MODE == 0) ? g_w1r : g_w2r;
    const float* __restrict__ W = Wbase + ((size_t)e * NTOT + n0) * KTOT;

    extern __shared__ __align__(16) char smem[];
    const uint32_t tb = smem_u32(smem);
    int* s_tok = (int*)(smem + NSTG * STAGE);

    const int tid  = threadIdx.x;
    const int wid  = tid >> 5;
    const int lane = tid & 31;
    const int grp  = lane >> 2;
    const int qid  = lane & 3;

    {
        int ml = mloc0 + tid;
        s_tok[tid] = (ml < cnt) ? g_tok[e * T_TOK + ml] : -1;
    }
    __syncthreads();

    uint32_t Ab[NSTG], Bb[NSTG];
#pragma unroll
    for (int i = 0; i < NSTG; i++) { Ab[i] = tb + i * STAGE; Bb[i] = Ab[i] + TILE_T; }

    // warp tile 64(M) x 64(N)
    const int m0w = (wid & 1) * 64;
    const int n0w = (wid >> 1) * 64;

    float c[4][8][4];
#pragma unroll
    for (int i = 0; i < 4; i++)
#pragma unroll
        for (int j = 0; j < 8; j++)
#pragma unroll
            for (int k = 0; k < 4; k++) c[i][j][k] = 0.f;

    constexpr int NST = KTOT / 32;
    load_stage<KTOT, MODE>(Ab[0], Bb[0], W, s_tok, mt, 0, tid);
    CP_COMMIT();
    load_stage<KTOT, MODE>(Ab[1], Bb[1], W, s_tok, mt, 32, tid);
    CP_COMMIT();

    uint32_t a[2][4][4], b[2][8][2];   // ks-level double-buffered fragments

    int sc = 0;                 // stage being consumed
    int sl = 2;                 // stage to load next
    for (int kt = 0; kt < NST; kt++) {
        if (kt == NST - 1) { CP_WAIT(0); } else { CP_WAIT(1); }
        __syncthreads();        // stage sc visible; all warps done with stage sl (consumed at kt-1)

        const uint32_t At = Ab[sc], Bt = Bb[sc];
        // ks0 peel: frags first so MMAs start ASAP; heavy cp.async issue after ks0.
        load_frags(At, Bt, 0, m0w, n0w, grp, qid, a[0], b[0]);
        load_frags(At, Bt, 8, m0w, n0w, grp, qid, a[1], b[1]);
#pragma unroll
        for (int nb = 0; nb < 8; nb++) {
#pragma unroll
            for (int mf = 0; mf < 4; mf++)
                MMA_TF32(c[mf][nb], a[0][mf], b[0][nb][0], b[0][nb][1]);
        }
        if (kt + 2 < NST) {
            load_stage<KTOT, MODE>(Ab[sl], Bb[sl], W, s_tok, mt, (kt + 2) * 32, tid);
            CP_COMMIT();
        }
#pragma unroll
        for (int ks = 1; ks < 4; ks++) {
            const int cur = ks & 1;
            if (ks < 3)
                load_frags(At, Bt, (ks + 1) * 8, m0w, n0w, grp, qid, a[cur ^ 1], b[cur ^ 1]);
#pragma unroll
            for (int nb = 0; nb < 8; nb++) {
#pragma unroll
                for (int mf = 0; mf < 4; mf++)
                    MMA_TF32(c[mf][nb], a[cur][mf], b[cur][nb][0], b[cur][nb][1]);
            }
        }
        sc = (sc + 1 == NSTG) ? 0 : sc + 1;
        sl = (sl + 1 == NSTG) ? 0 : sl + 1;
    }

    // ---- epilogue ----
#pragma unroll
    for (int mf = 0; mf < 4; mf++) {
#pragma unroll
        for (int half = 0; half < 2; half++) {
            int row = m0w + mf * 16 + half * 8 + grp;
            if (MODE == 0) {
                if (mloc0 + row < cnt) {
                    float* op = g_h + (size_t)(mt * 128 + row) * N1 + n0 + n0w + qid * 2;
#pragma unroll
                    for (int nb = 0; nb < 8; nb++)
                        *(float2*)(op + nb * 8) = make_float2(c[mf][nb][half * 2],
                                                              c[mf][nb][half * 2 + 1]);
                }
            } else {
                if (s_tok[row] >= 0) {
                    float* op = g_h + (size_t)(mt * 128 + row) * D_DIM + n0 + n0w + qid * 2;
#pragma unroll
                    for (int nb = 0; nb < 8; nb++)
                        *(float2*)(op + nb * 8) = make_float2(c[mf][nb][half * 2],
                                                              c[mf][nb][half * 2 + 1]);
                }
            }
        }
    }
}

// ---------------- host ----------------
extern "C" void kernel_launch(void* const* d_in, const int* in_sizes, int n_in,
                              void* d_out, int out_size) {
    const float* x   = (const float*)d_in[0];
    const float* gw  = (const float*)d_in[1];
    const float* wv1 = (const float*)d_in[2];
    const float* w2  = (const float*)d_in[3];
    float* out = (float*)d_out;

    cudaFuncSetAttribute(moe_gemm_tf32<D_DIM, 0>, cudaFuncAttributeMaxDynamicSharedMemorySize, DSMEM_SZ);
    cudaFuncSetAttribute(moe_gemm_tf32<F_DIM, 1>, cudaFuncAttributeMaxDynamicSharedMemorySize, DSMEM_SZ);

    size_t totq = (W1E + W2E + XE) / 4;
    cvt_all_kernel<<<(unsigned)((totq + 255) / 256), 256>>>(x, wv1, w2);
    gate_kernel<<<(T_TOK * 32) / 256, 256>>>(x, gw);
    offs_kernel<<<1, 1>>>();
    moe_gemm_tf32<D_DIM, 0><<<dim3(N1 / 128, MT_MAX), 128, DSMEM_SZ>>>(nullptr);   // 4th: ncu slot
    silu_kernel<<<(MAX_ROWS * (F_DIM / 4) + 255) / 256, 256>>>();
    moe_gemm_tf32<F_DIM, 1><<<dim3(D_DIM / 128, MT_MAX), 128, DSMEM_SZ>>>(nullptr);
    combine_kernel<<<(T_TOK * D_DIM / 4 + 255) / 256, 256>>>(out);
}

// round 14
// speedup vs baseline: 1.0429x; 1.0429x over previous
#include <cuda_runtime.h>
#include <cuda_bf16.h>
#include <math.h>
#include <stdint.h>

#define T_TOK 8192
#define D_DIM 2048
#define F_DIM 3584
#define E_NUM 8
#define N1 (2 * F_DIM)          // 7168
#define MT_MAX 136
#define MAX_ROWS (MT_MAX * 128)

#define W1E ((size_t)E_NUM * N1 * D_DIM)
#define W2E ((size_t)E_NUM * D_DIM * F_DIM)
#define XE  ((size_t)T_TOK * D_DIM)

// ---------------- scratch ----------------
__device__ float g_h[(size_t)MAX_ROWS * N1];     // gemm1 out; later reused as Y (gemm2 out)
__device__ float g_act[(size_t)MAX_ROWS * F_DIM];
__device__ float g_w1r[W1E];
__device__ float g_w2r[W2E];
__device__ float g_xr[XE];
__device__ int   g_tok[E_NUM * T_TOK];
__device__ int   g_slot[2 * T_TOK];              // per token: (e<<13)|p
__device__ float g_wt[2 * T_TOK];
__device__ int   g_cnt[E_NUM];
__device__ int   g_ts[E_NUM + 1];

// ---------------- helpers ----------------
__device__ __forceinline__ uint32_t smem_u32(const void* p) {
    uint32_t a;
    asm("{ .reg .u64 t; cvta.to.shared.u64 t, %1; cvt.u32.u64 %0, t; }" : "=r"(a) : "l"(p));
    return a;
}
__device__ __forceinline__ float tf32r(float v) {
    uint32_t r;
    asm("cvt.rna.tf32.f32 %0, %1;" : "=r"(r) : "f"(v));
    return __uint_as_float(r);
}
#define CP_ASYNC16(dst, src, sz) \
    asm volatile("cp.async.cg.shared.global [%0], [%1], 16, %2;" :: "r"(dst), "l"(src), "r"(sz) : "memory")
#define CP_COMMIT() asm volatile("cp.async.commit_group;" ::: "memory")
#define CP_WAIT(n)  asm volatile("cp.async.wait_group %0;" :: "n"(n) : "memory")

// padded + chunk-permuted row: stride 144B; 16B-chunk kc stored at (kc + 2*row)&7
#define RPB 144
#define TILE_T (128 * RPB)        // 18432 B (A or B tile: 128 rows x 32 K)
#define STAGE  (2 * TILE_T)       // 36864 B
#define NSTG   3
#define DSMEM_SZ (NSTG * STAGE + 1024)

__device__ __forceinline__ uint32_t taddr(uint32_t base, int row, int col) {
    int pc = ((col >> 2) + 2 * row) & 7;
    return base + row * RPB + pc * 16 + (col & 3) * 4;
}
__device__ __forceinline__ uint32_t lds_raw(uint32_t a) {
    uint32_t v;
    asm volatile("ld.shared.b32 %0, [%1];" : "=r"(v) : "r"(a));
    return v;
}
#define MMA_TF32(c, a, b0, b1)                                                      \
    asm volatile("mma.sync.aligned.m16n8k8.row.col.f32.tf32.tf32.f32 "              \
        "{%0,%1,%2,%3}, {%4,%5,%6,%7}, {%8,%9}, {%0,%1,%2,%3};"                     \
        : "+f"((c)[0]), "+f"((c)[1]), "+f"((c)[2]), "+f"((c)[3])                    \
        : "r"((a)[0]), "r"((a)[1]), "r"((a)[2]), "r"((a)[3]), "r"(b0), "r"(b1))

// ---------------- pre-pass ----------------
__global__ void cvt_all_kernel(const float* __restrict__ x,
                               const float* __restrict__ wv1,
                               const float* __restrict__ w2) {
    if (blockIdx.x == 0 && threadIdx.x < E_NUM) g_cnt[threadIdx.x] = 0;
    const size_t W1Q = W1E / 4, W2Q = W2E / 4, XQ = XE / 4;
    size_t i = (size_t)blockIdx.x * blockDim.x + threadIdx.x;
    const float4* src;
    float4* dst;
    if (i < W1Q) {
        src = (const float4*)wv1 + i;             dst = (float4*)g_w1r + i;
    } else if (i < W1Q + W2Q) {
        src = (const float4*)w2 + (i - W1Q);      dst = (float4*)g_w2r + (i - W1Q);
    } else if (i < W1Q + W2Q + XQ) {
        src = (const float4*)x + (i - W1Q - W2Q); dst = (float4*)g_xr + (i - W1Q - W2Q);
    } else return;
    float4 v = *src;
    v.x = tf32r(v.x); v.y = tf32r(v.y); v.z = tf32r(v.z); v.w = tf32r(v.w);
    *dst = v;
}

// ---------------- gating ----------------
__global__ void gate_kernel(const float* __restrict__ x, const float* __restrict__ gw) {
    int warp = (blockIdx.x * blockDim.x + threadIdx.x) >> 5;
    int lane = threadIdx.x & 31;
    if (warp >= T_TOK) return;
    const float* xr = x + (size_t)warp * D_DIM;
    float acc[E_NUM];
#pragma unroll
    for (int e = 0; e < E_NUM; e++) acc[e] = 0.f;
    for (int d = lane; d < D_DIM; d += 32) {
        float xv = xr[d];
#pragma unroll
        for (int e = 0; e < E_NUM; e++) acc[e] += xv * gw[e * D_DIM + d];
    }
#pragma unroll
    for (int e = 0; e < E_NUM; e++)
#pragma unroll
        for (int o = 16; o > 0; o >>= 1) acc[e] += __shfl_xor_sync(0xFFFFFFFFu, acc[e], o);
    if (lane == 0) {
        int i1 = 0; float l1 = acc[0];
#pragma unroll
        for (int e = 1; e < E_NUM; e++) if (acc[e] > l1) { l1 = acc[e]; i1 = e; }
        int i2 = -1; float l2 = -3.4e38f;
#pragma unroll
        for (int e = 0; e < E_NUM; e++) if (e != i1 && acc[e] > l2) { l2 = acc[e]; i2 = e; }
        float w1 = 1.f / (1.f + expf(l2 - l1));
        float w2 = 1.f - w1;
        int p1 = atomicAdd(&g_cnt[i1], 1);
        g_tok[i1 * T_TOK + p1] = warp;
        g_slot[2 * warp] = (i1 << 13) | p1; g_wt[2 * warp] = w1;
        int p2 = atomicAdd(&g_cnt[i2], 1);
        g_tok[i2 * T_TOK + p2] = warp;
        g_slot[2 * warp + 1] = (i2 << 13) | p2; g_wt[2 * warp + 1] = w2;
    }
}

__global__ void offs_kernel() {
    int t = 0;
    for (int e = 0; e < E_NUM; e++) { g_ts[e] = t; t += (g_cnt[e] + 127) >> 7; }
    g_ts[E_NUM] = t;
}

// flat silu: one float4 per thread over all padded rows (garbage rows are
// row-isolated and never stored downstream: gemm2 epilogue guards on s_tok).
__global__ void silu_kernel() {
    const int F4 = F_DIM / 4;
    int idx = blockIdx.x * blockDim.x + threadIdx.x;
    int row = idx / F4;
    if (row >= g_ts[E_NUM] * 128) return;
    int c4 = idx % F4;
    const float4* gp = (const float4*)(g_h + (size_t)row * N1) + c4;
    float4 g = gp[0];
    float4 u = gp[F_DIM / 4];
    float4 o;
    o.x = tf32r((g.x / (1.f + expf(-g.x))) * u.x);
    o.y = tf32r((g.y / (1.f + expf(-g.y))) * u.y);
    o.z = tf32r((g.z / (1.f + expf(-g.z))) * u.z);
    o.w = tf32r((g.w / (1.f + expf(-g.w))) * u.w);
    ((float4*)(g_act + (size_t)row * F_DIM))[c4] = o;
}

// final: out[t] = w1*Y[r1] + w2*Y[r2]
__global__ void combine_kernel(float* __restrict__ out) {
    const int C4 = D_DIM / 4;
    int idx = blockIdx.x * blockDim.x + threadIdx.x;
    if (idx >= T_TOK * C4) return;
    int t = idx / C4, c = idx % C4;
    int s1 = g_slot[2 * t], s2 = g_slot[2 * t + 1];
    float w1 = g_wt[2 * t], w2 = g_wt[2 * t + 1];
    int r1 = g_ts[s1 >> 13] * 128 + (s1 & 8191);
    int r2 = g_ts[s2 >> 13] * 128 + (s2 & 8191);
    float4 y1 = *((const float4*)g_h + (size_t)r1 * C4 + c);
    float4 y2 = *((const float4*)g_h + (size_t)r2 * C4 + c);
    float4 o;
    o.x = w1 * y1.x + w2 * y2.x;
    o.y = w1 * y1.y + w2 * y2.y;
    o.z = w1 * y1.z + w2 * y2.z;
    o.w = w1 * y1.w + w2 * y2.w;
    ((float4*)out)[idx] = o;
}

// ---------------- TF32 GEMM: CTA 128M x 128N, 4 warps (64x64), 3-stage, 2 CTA/SM ----------------
// R11 mainloop: cp.async issued immediately after barrier; ks-level frag double-buffering.
// MODE 0: A = g_xr gathered, W = g_w1r -> g_h[.,N1]       (K=2048, N=7168)
// MODE 1: A = g_act,         W = g_w2r -> Y=g_h[.,D_DIM]  (K=3584, N=2048)
template <int KTOT, int MODE>
__device__ __forceinline__ void load_stage(uint32_t Ab, uint32_t Bb,
                                           const float* __restrict__ W,
                                           const int* s_tok, int mt, int k0, int tid) {
#pragma unroll
    for (int i = 0; i < 16; i++) {
        int id = tid + 128 * i;
        if (id < 1024) {                      // A: 128 rows x 8 chunks
            int r = id >> 3, kc = id & 7;
            int pc = (kc + 2 * r) & 7;
            uint32_t ad = Ab + r * RPB + pc * 16;
            if (MODE == 0) {
                int tok = s_tok[r];
                const float* src = g_xr + (size_t)(tok < 0 ? 0 : tok) * KTOT + k0 + kc * 4;
                int sz = (tok >= 0) ? 16 : 0;
                CP_ASYNC16(ad, src, sz);
            } else {
                const float* src = g_act + (size_t)(mt * 128 + r) * KTOT + k0 + kc * 4;
                CP_ASYNC16(ad, src, 16);
            }
        } else {                              // B: 128 rows x 8 chunks
            int ib = id - 1024;
            int r = ib >> 3, kc = ib & 7;
            int pc = (kc + 2 * r) & 7;
            uint32_t bd = Bb + r * RPB + pc * 16;
            const float* bs = W + (size_t)r * KTOT + k0 + kc * 4;
            CP_ASYNC16(bd, bs, 16);
        }
    }
}

__device__ __forceinline__ void load_frags(uint32_t At, uint32_t Bt, int kb,
                                           int m0w, int n0w, int grp, int qid,
                                           uint32_t a[4][4], uint32_t b[8][2]) {
#pragma unroll
    for (int mf = 0; mf < 4; mf++) {
        int row = m0w + mf * 16 + grp;
        a[mf][0] = lds_raw(taddr(At, row,     kb + qid));
        a[mf][1] = lds_raw(taddr(At, row + 8, kb + qid));
        a[mf][2] = lds_raw(taddr(At, row,     kb + qid + 4));
        a[mf][3] = lds_raw(taddr(At, row + 8, kb + qid + 4));
    }
#pragma unroll
    for (int nb = 0; nb < 8; nb++) {
        int n = n0w + nb * 8 + grp;
        b[nb][0] = lds_raw(taddr(Bt, n, kb + qid));
        b[nb][1] = lds_raw(taddr(Bt, n, kb + qid + 4));
    }
}

template <int KTOT, int MODE>
__global__ void __launch_bounds__(128, 2) moe_gemm_tf32(float* __restrict__ Outp) {
    const int mt = blockIdx.y;
    int ts[E_NUM + 1];
#pragma unroll
    for (int i = 0; i <= E_NUM; i++) ts[i] = g_ts[i];
    if (mt >= ts[E_NUM]) return;
    int e = 0;
#pragma unroll
    for (int i = 0; i < E_NUM; i++) if (mt >= ts[i + 1]) e = i + 1;
    const int cnt = g_cnt[e];
    const int mloc0 = (mt - ts[e]) * 128;
    const int n0 = blockIdx.x * 128;
    const int NTOT = gridDim.x * 128;
    const float* __restrict__ Wbase = (MODE == 0) ? g_w1r : g_w2r;
    const float* __restrict__ W = Wbase + ((size_t)e * NTOT + n0) * KTOT;

    extern __shared__ __align__(16) char smem[];
    const uint32_t tb = smem_u32(smem);
    int* s_tok = (int*)(smem + NSTG * STAGE);

    const int tid  = threadIdx.x;
    const int wid  = tid >> 5;
    const int lane = tid & 31;
    const int grp  = lane >> 2;
    const int qid  = lane & 3;

    {
        int ml = mloc0 + tid;
        s_tok[tid] = (ml < cnt) ? g_tok[e * T_TOK + ml] : -1;
    }
    __syncthreads();

    uint32_t Ab[NSTG], Bb[NSTG];
#pragma unroll
    for (int i = 0; i < NSTG; i++) { Ab[i] = tb + i * STAGE; Bb[i] = Ab[i] + TILE_T; }

    // warp tile 64(M) x 64(N)
    const int m0w = (wid & 1) * 64;
    const int n0w = (wid >> 1) * 64;

    float c[4][8][4];
#pragma unroll
    for (int i = 0; i < 4; i++)
#pragma unroll
        for (int j = 0; j < 8; j++)
#pragma unroll
            for (int k = 0; k < 4; k++) c[i][j][k] = 0.f;

    constexpr int NST = KTOT / 32;
    load_stage<KTOT, MODE>(Ab[0], Bb[0], W, s_tok, mt, 0, tid);
    CP_COMMIT();
    load_stage<KTOT, MODE>(Ab[1], Bb[1], W, s_tok, mt, 32, tid);
    CP_COMMIT();

    uint32_t a[2][4][4], b[2][8][2];   // ks-level double-buffered fragments

    int sc = 0;                 // stage being consumed
    int sl = 2;                 // stage to load next
    for (int kt = 0; kt < NST; kt++) {
        if (kt == NST - 1) { CP_WAIT(0); } else { CP_WAIT(1); }
        __syncthreads();        // stage sc visible; all warps done with stage sl (consumed at kt-1)

        if (kt + 2 < NST) {
            load_stage<KTOT, MODE>(Ab[sl], Bb[sl], W, s_tok, mt, (kt + 2) * 32, tid);
            CP_COMMIT();
        }

        const uint32_t At = Ab[sc], Bt = Bb[sc];
        load_frags(At, Bt, 0, m0w, n0w, grp, qid, a[0], b[0]);
#pragma unroll
        for (int ks = 0; ks < 4; ks++) {
            const int cur = ks & 1;
            if (ks < 3)
                load_frags(At, Bt, (ks + 1) * 8, m0w, n0w, grp, qid, a[cur ^ 1], b[cur ^ 1]);
#pragma unroll
            for (int nb = 0; nb < 8; nb++) {
#pragma unroll
                for (int mf = 0; mf < 4; mf++)
                    MMA_TF32(c[mf][nb], a[cur][mf], b[cur][nb][0], b[cur][nb][1]);
            }
        }
        sc = (sc + 1 == NSTG) ? 0 : sc + 1;
        sl = (sl + 1 == NSTG) ? 0 : sl + 1;
    }

    // ---- epilogue ----
#pragma unroll
    for (int mf = 0; mf < 4; mf++) {
#pragma unroll
        for (int half = 0; half < 2; half++) {
            int row = m0w + mf * 16 + half * 8 + grp;
            if (MODE == 0) {
                if (mloc0 + row < cnt) {
                    float* op = g_h + (size_t)(mt * 128 + row) * N1 + n0 + n0w + qid * 2;
#pragma unroll
                    for (int nb = 0; nb < 8; nb++)
                        *(float2*)(op + nb * 8) = make_float2(c[mf][nb][half * 2],
                                                              c[mf][nb][half * 2 + 1]);
                }
            } else {
                if (s_tok[row] >= 0) {
                    float* op = g_h + (size_t)(mt * 128 + row) * D_DIM + n0 + n0w + qid * 2;
#pragma unroll
                    for (int nb = 0; nb < 8; nb++)
                        *(float2*)(op + nb * 8) = make_float2(c[mf][nb][half * 2],
                                                              c[mf][nb][half * 2 + 1]);
                }
            }
        }
    }
}

// ---------------- host ----------------
extern "C" void kernel_launch(void* const* d_in, const int* in_sizes, int n_in,
                              void* d_out, int out_size) {
    const float* x   = (const float*)d_in[0];
    const float* gw  = (const float*)d_in[1];
    const float* wv1 = (const float*)d_in[2];
    const float* w2  = (const float*)d_in[3];
    float* out = (float*)d_out;

    cudaFuncSetAttribute(moe_gemm_tf32<D_DIM, 0>, cudaFuncAttributeMaxDynamicSharedMemorySize, DSMEM_SZ);
    cudaFuncSetAttribute(moe_gemm_tf32<F_DIM, 1>, cudaFuncAttributeMaxDynamicSharedMemorySize, DSMEM_SZ);

    size_t totq = (W1E + W2E + XE) / 4;
    cvt_all_kernel<<<(unsigned)((totq + 255) / 256), 256>>>(x, wv1, w2);
    gate_kernel<<<(T_TOK * 32) / 256, 256>>>(x, gw);
    offs_kernel<<<1, 1>>>();
    moe_gemm_tf32<D_DIM, 0><<<dim3(N1 / 128, MT_MAX), 128, DSMEM_SZ>>>(nullptr);   // 4th: ncu slot
    silu_kernel<<<(MAX_ROWS * (F_DIM / 4) + 255) / 256, 256>>>();
    moe_gemm_tf32<F_DIM, 1><<<dim3(D_DIM / 128, MT_MAX), 128, DSMEM_SZ>>>(nullptr);
    combine_kernel<<<(T_TOK * D_DIM / 4 + 255) / 256, 256>>>(out);
}

// round 15
// speedup vs baseline: 1.0460x; 1.0030x over previous
#include <cuda_runtime.h>
#include <cuda_bf16.h>
#include <math.h>
#include <stdint.h>

#define T_TOK 8192
#define D_DIM 2048
#define F_DIM 3584
#define E_NUM 8
#define N1 (2 * F_DIM)          // 7168
#define MT_MAX 136
#define MAX_ROWS (MT_MAX * 128)

#define W1E ((size_t)E_NUM * N1 * D_DIM)
#define W2E ((size_t)E_NUM * D_DIM * F_DIM)
#define XE  ((size_t)T_TOK * D_DIM)

#define GATE_BLKS (T_TOK / 8)                    // 1024 blocks, warp/token, 256 thr
#define CVT_QUADS ((W1E + W2E + XE) / 4)
#define CVT_BLKS  ((unsigned)((CVT_QUADS + 255) / 256))

// ---------------- scratch ----------------
__device__ float g_h[(size_t)MAX_ROWS * N1];     // gemm1 out; later reused as Y (gemm2 out)
__device__ float g_act[(size_t)MAX_ROWS * F_DIM];
__device__ float g_w1r[W1E];
__device__ float g_w2r[W2E];
__device__ float g_xr[XE];
__device__ int   g_tok[E_NUM * T_TOK];
__device__ int   g_slot[2 * T_TOK];              // per token: (e<<13)|p
__device__ float g_wt[2 * T_TOK];
__device__ int   g_cnt[E_NUM];
__device__ int   g_ts[E_NUM + 1];

// ---------------- helpers ----------------
__device__ __forceinline__ uint32_t smem_u32(const void* p) {
    uint32_t a;
    asm("{ .reg .u64 t; cvta.to.shared.u64 t, %1; cvt.u32.u64 %0, t; }" : "=r"(a) : "l"(p));
    return a;
}
__device__ __forceinline__ float tf32r(float v) {
    uint32_t r;
    asm("cvt.rna.tf32.f32 %0, %1;" : "=r"(r) : "f"(v));
    return __uint_as_float(r);
}
#define CP_ASYNC16(dst, src, sz) \
    asm volatile("cp.async.cg.shared.global [%0], [%1], 16, %2;" :: "r"(dst), "l"(src), "r"(sz) : "memory")
#define CP_COMMIT() asm volatile("cp.async.commit_group;" ::: "memory")
#define CP_WAIT(n)  asm volatile("cp.async.wait_group %0;" :: "n"(n) : "memory")

// padded + chunk-permuted row: stride 144B; 16B-chunk kc stored at (kc + 2*row)&7
#define RPB 144
#define TILE_T (128 * RPB)        // 18432 B (A or B tile: 128 rows x 32 K)
#define STAGE  (2 * TILE_T)       // 36864 B
#define NSTG   3
#define DSMEM_SZ (NSTG * STAGE + 1024)

__device__ __forceinline__ uint32_t taddr(uint32_t base, int row, int col) {
    int pc = ((col >> 2) + 2 * row) & 7;
    return base + row * RPB + pc * 16 + (col & 3) * 4;
}
__device__ __forceinline__ uint32_t lds_raw(uint32_t a) {
    uint32_t v;
    asm volatile("ld.shared.b32 %0, [%1];" : "=r"(v) : "r"(a));
    return v;
}
#define MMA_TF32(c, a, b0, b1)                                                      \
    asm volatile("mma.sync.aligned.m16n8k8.row.col.f32.tf32.tf32.f32 "              \
        "{%0,%1,%2,%3}, {%4,%5,%6,%7}, {%8,%9}, {%0,%1,%2,%3};"                     \
        : "+f"((c)[0]), "+f"((c)[1]), "+f"((c)[2]), "+f"((c)[3])                    \
        : "r"((a)[0]), "r"((a)[1]), "r"((a)[2]), "r"((a)[3]), "r"(b0), "r"(b1))

// ---------------- init ----------------
__global__ void init_kernel() { if (threadIdx.x < E_NUM) g_cnt[threadIdx.x] = 0; }

// ---------------- fused gate + tf32 rounding pre-pass ----------------
// blocks [0, GATE_BLKS): gating (warp per token)
// blocks [GATE_BLKS, ...): round wv1/w2/x quads into g_w1r/g_w2r/g_xr
__global__ void fused_pre_kernel(const float* __restrict__ x,
                                 const float* __restrict__ gw,
                                 const float* __restrict__ wv1,
                                 const float* __restrict__ w2) {
    if (blockIdx.x < GATE_BLKS) {
        int warp = (blockIdx.x * blockDim.x + threadIdx.x) >> 5;
        int lane = threadIdx.x & 31;
        const float* xr = x + (size_t)warp * D_DIM;
        float acc[E_NUM];
#pragma unroll
        for (int e = 0; e < E_NUM; e++) acc[e] = 0.f;
        for (int d = lane; d < D_DIM; d += 32) {
            float xv = xr[d];
#pragma unroll
            for (int e = 0; e < E_NUM; e++) acc[e] += xv * gw[e * D_DIM + d];
        }
#pragma unroll
        for (int e = 0; e < E_NUM; e++)
#pragma unroll
            for (int o = 16; o > 0; o >>= 1) acc[e] += __shfl_xor_sync(0xFFFFFFFFu, acc[e], o);
        if (lane == 0) {
            int i1 = 0; float l1 = acc[0];
#pragma unroll
            for (int e = 1; e < E_NUM; e++) if (acc[e] > l1) { l1 = acc[e]; i1 = e; }
            int i2 = -1; float l2 = -3.4e38f;
#pragma unroll
            for (int e = 0; e < E_NUM; e++) if (e != i1 && acc[e] > l2) { l2 = acc[e]; i2 = e; }
            float w1 = 1.f / (1.f + expf(l2 - l1));
            float w2v = 1.f - w1;
            int p1 = atomicAdd(&g_cnt[i1], 1);
            g_tok[i1 * T_TOK + p1] = warp;
            g_slot[2 * warp] = (i1 << 13) | p1; g_wt[2 * warp] = w1;
            int p2 = atomicAdd(&g_cnt[i2], 1);
            g_tok[i2 * T_TOK + p2] = warp;
            g_slot[2 * warp + 1] = (i2 << 13) | p2; g_wt[2 * warp + 1] = w2v;
        }
        return;
    }
    const size_t W1Q = W1E / 4, W2Q = W2E / 4, XQ = XE / 4;
    size_t i = (size_t)(blockIdx.x - GATE_BLKS) * blockDim.x + threadIdx.x;
    const float4* src;
    float4* dst;
    if (i < W1Q) {
        src = (const float4*)wv1 + i;             dst = (float4*)g_w1r + i;
    } else if (i < W1Q + W2Q) {
        src = (const float4*)w2 + (i - W1Q);      dst = (float4*)g_w2r + (i - W1Q);
    } else if (i < W1Q + W2Q + XQ) {
        src = (const float4*)x + (i - W1Q - W2Q); dst = (float4*)g_xr + (i - W1Q - W2Q);
    } else return;
    float4 v = *src;
    v.x = tf32r(v.x); v.y = tf32r(v.y); v.z = tf32r(v.z); v.w = tf32r(v.w);
    *dst = v;
}

__global__ void offs_kernel() {
    int t = 0;
    for (int e = 0; e < E_NUM; e++) { g_ts[e] = t; t += (g_cnt[e] + 127) >> 7; }
    g_ts[E_NUM] = t;
}

// flat silu: one float4 per thread over all padded rows (garbage rows are
// row-isolated and never stored downstream: gemm2 epilogue guards on s_tok).
__global__ void silu_kernel() {
    const int F4 = F_DIM / 4;
    int idx = blockIdx.x * blockDim.x + threadIdx.x;
    int row = idx / F4;
    if (row >= g_ts[E_NUM] * 128) return;
    int c4 = idx % F4;
    const float4* gp = (const float4*)(g_h + (size_t)row * N1) + c4;
    float4 g = gp[0];
    float4 u = gp[F_DIM / 4];
    float4 o;
    o.x = tf32r((g.x / (1.f + expf(-g.x))) * u.x);
    o.y = tf32r((g.y / (1.f + expf(-g.y))) * u.y);
    o.z = tf32r((g.z / (1.f + expf(-g.z))) * u.z);
    o.w = tf32r((g.w / (1.f + expf(-g.w))) * u.w);
    ((float4*)(g_act + (size_t)row * F_DIM))[c4] = o;
}

// final: out[t] = w1*Y[r1] + w2*Y[r2]
__global__ void combine_kernel(float* __restrict__ out) {
    const int C4 = D_DIM / 4;
    int idx = blockIdx.x * blockDim.x + threadIdx.x;
    if (idx >= T_TOK * C4) return;
    int t = idx / C4, c = idx % C4;
    int s1 = g_slot[2 * t], s2 = g_slot[2 * t + 1];
    float w1 = g_wt[2 * t], w2 = g_wt[2 * t + 1];
    int r1 = g_ts[s1 >> 13] * 128 + (s1 & 8191);
    int r2 = g_ts[s2 >> 13] * 128 + (s2 & 8191);
    float4 y1 = *((const float4*)g_h + (size_t)r1 * C4 + c);
    float4 y2 = *((const float4*)g_h + (size_t)r2 * C4 + c);
    float4 o;
    o.x = w1 * y1.x + w2 * y2.x;
    o.y = w1 * y1.y + w2 * y2.y;
    o.z = w1 * y1.z + w2 * y2.z;
    o.w = w1 * y1.w + w2 * y2.w;
    ((float4*)out)[idx] = o;
}

// ---------------- TF32 GEMM: CTA 128M x 128N, 4 warps (64x64), 3-stage, 2 CTA/SM ----------------
// R11/R13 mainloop: cp.async issued immediately after barrier; ks-level frag double-buffering.
// MODE 0: A = g_xr gathered, W = g_w1r -> g_h[.,N1]       (K=2048, N=7168)
// MODE 1: A = g_act,         W = g_w2r -> Y=g_h[.,D_DIM]  (K=3584, N=2048)
template <int KTOT, int MODE>
__device__ __forceinline__ void load_stage(uint32_t Ab, uint32_t Bb,
                                           const float* __restrict__ W,
                                           const int* s_tok, int mt, int k0, int tid) {
#pragma unroll
    for (int i = 0; i < 16; i++) {
        int id = tid + 128 * i;
        if (id < 1024) {                      // A: 128 rows x 8 chunks
            int r = id >> 3, kc = id & 7;
            int pc = (kc + 2 * r) & 7;
            uint32_t ad = Ab + r * RPB + pc * 16;
            if (MODE == 0) {
                int tok = s_tok[r];
                const float* src = g_xr + (size_t)(tok < 0 ? 0 : tok) * KTOT + k0 + kc * 4;
                int sz = (tok >= 0) ? 16 : 0;
                CP_ASYNC16(ad, src, sz);
            } else {
                const float* src = g_act + (size_t)(mt * 128 + r) * KTOT + k0 + kc * 4;
                CP_ASYNC16(ad, src, 16);
            }
        } else {                              // B: 128 rows x 8 chunks
            int ib = id - 1024;
            int r = ib >> 3, kc = ib & 7;
            int pc = (kc + 2 * r) & 7;
            uint32_t bd = Bb + r * RPB + pc * 16;
            const float* bs = W + (size_t)r * KTOT + k0 + kc * 4;
            CP_ASYNC16(bd, bs, 16);
        }
    }
}

__device__ __forceinline__ void load_frags(uint32_t At, uint32_t Bt, int kb,
                                           int m0w, int n0w, int grp, int qid,
                                           uint32_t a[4][4], uint32_t b[8][2]) {
#pragma unroll
    for (int mf = 0; mf < 4; mf++) {
        int row = m0w + mf * 16 + grp;
        a[mf][0] = lds_raw(taddr(At, row,     kb + qid));
        a[mf][1] = lds_raw(taddr(At, row + 8, kb + qid));
        a[mf][2] = lds_raw(taddr(At, row,     kb + qid + 4));
        a[mf][3] = lds_raw(taddr(At, row + 8, kb + qid + 4));
    }
#pragma unroll
    for (int nb = 0; nb < 8; nb++) {
        int n = n0w + nb * 8 + grp;
        b[nb][0] = lds_raw(taddr(Bt, n, kb + qid));
        b[nb][1] = lds_raw(taddr(Bt, n, kb + qid + 4));
    }
}

template <int KTOT, int MODE>
__global__ void __launch_bounds__(128, 2) moe_gemm_tf32(float* __restrict__ Outp) {
    const int mt = blockIdx.y;
    int ts[E_NUM + 1];
#pragma unroll
    for (int i = 0; i <= E_NUM; i++) ts[i] = g_ts[i];
    if (mt >= ts[E_NUM]) return;
    int e = 0;
#pragma unroll
    for (int i = 0; i < E_NUM; i++) if (mt >= ts[i + 1]) e = i + 1;
    const int cnt = g_cnt[e];
    const int mloc0 = (mt - ts[e]) * 128;
    const int n0 = blockIdx.x * 128;
    const int NTOT = gridDim.x * 128;
    const float* __restrict__ Wbase = (MODE == 0) ? g_w1r : g_w2r;
    const float* __restrict__ W = Wbase + ((size_t)e * NTOT + n0) * KTOT;

    extern __shared__ __align__(16) char smem[];
    const uint32_t tb = smem_u32(smem);
    int* s_tok = (int*)(smem + NSTG * STAGE);

    const int tid  = threadIdx.x;
    const int wid  = tid >> 5;
    const int lane = tid & 31;
    const int grp  = lane >> 2;
    const int qid  = lane & 3;

    {
        int ml = mloc0 + tid;
        s_tok[tid] = (ml < cnt) ? g_tok[e * T_TOK + ml] : -1;
    }
    __syncthreads();

    uint32_t Ab[NSTG], Bb[NSTG];
#pragma unroll
    for (int i = 0; i < NSTG; i++) { Ab[i] = tb + i * STAGE; Bb[i] = Ab[i] + TILE_T; }

    // warp tile 64(M) x 64(N)
    const int m0w = (wid & 1) * 64;
    const int n0w = (wid >> 1) * 64;

    float c[4][8][4];
#pragma unroll
    for (int i = 0; i < 4; i++)
#pragma unroll
        for (int j = 0; j < 8; j++)
#pragma unroll
            for (int k = 0; k < 4; k++) c[i][j][k] = 0.f;

    constexpr int NST = KTOT / 32;
    load_stage<KTOT, MODE>(Ab[0], Bb[0], W, s_tok, mt, 0, tid);
    CP_COMMIT();
    load_stage<KTOT, MODE>(Ab[1], Bb[1], W, s_tok, mt, 32, tid);
    CP_COMMIT();

    uint32_t a[2][4][4], b[2][8][2];   // ks-level double-buffered fragments

    int sc = 0;                 // stage being consumed
    int sl = 2;                 // stage to load next
    for (int kt = 0; kt < NST; kt++) {
        if (kt == NST - 1) { CP_WAIT(0); } else { CP_WAIT(1); }
        __syncthreads();        // stage sc visible; all warps done with stage sl (consumed at kt-1)

        if (kt + 2 < NST) {
            load_stage<KTOT, MODE>(Ab[sl], Bb[sl], W, s_tok, mt, (kt + 2) * 32, tid);
            CP_COMMIT();
        }

        const uint32_t At = Ab[sc], Bt = Bb[sc];
        load_frags(At, Bt, 0, m0w, n0w, grp, qid, a[0], b[0]);
#pragma unroll
        for (int ks = 0; ks < 4; ks++) {
            const int cur = ks & 1;
            if (ks < 3)
                load_frags(At, Bt, (ks + 1) * 8, m0w, n0w, grp, qid, a[cur ^ 1], b[cur ^ 1]);
#pragma unroll
            for (int nb = 0; nb < 8; nb++) {
#pragma unroll
                for (int mf = 0; mf < 4; mf++)
                    MMA_TF32(c[mf][nb], a[cur][mf], b[cur][nb][0], b[cur][nb][1]);
            }
        }
        sc = (sc + 1 == NSTG) ? 0 : sc + 1;
        sl = (sl + 1 == NSTG) ? 0 : sl + 1;
    }

    // ---- epilogue ----
#pragma unroll
    for (int mf = 0; mf < 4; mf++) {
#pragma unroll
        for (int half = 0; half < 2; half++) {
            int row = m0w + mf * 16 + half * 8 + grp;
            if (MODE == 0) {
                if (mloc0 + row < cnt) {
                    float* op = g_h + (size_t)(mt * 128 + row) * N1 + n0 + n0w + qid * 2;
#pragma unroll
                    for (int nb = 0; nb < 8; nb++)
                        *(float2*)(op + nb * 8) = make_float2(c[mf][nb][half * 2],
                                                              c[mf][nb][half * 2 + 1]);
                }
            } else {
                if (s_tok[row] >= 0) {
                    float* op = g_h + (size_t)(mt * 128 + row) * D_DIM + n0 + n0w + qid * 2;
#pragma unroll
                    for (int nb = 0; nb < 8; nb++)
                        *(float2*)(op + nb * 8) = make_float2(c[mf][nb][half * 2],
                                                              c[mf][nb][half * 2 + 1]);
                }
            }
        }
    }
}

// ---------------- host ----------------
extern "C" void kernel_launch(void* const* d_in, const int* in_sizes, int n_in,
                              void* d_out, int out_size) {
    const float* x   = (const float*)d_in[0];
    const float* gw  = (const float*)d_in[1];
    const float* wv1 = (const float*)d_in[2];
    const float* w2  = (const float*)d_in[3];
    float* out = (float*)d_out;

    cudaFuncSetAttribute(moe_gemm_tf32<D_DIM, 0>, cudaFuncAttributeMaxDynamicSharedMemorySize, DSMEM_SZ);
    cudaFuncSetAttribute(moe_gemm_tf32<F_DIM, 1>, cudaFuncAttributeMaxDynamicSharedMemorySize, DSMEM_SZ);

    init_kernel<<<1, 32>>>();
    fused_pre_kernel<<<GATE_BLKS + CVT_BLKS, 256>>>(x, gw, wv1, w2);
    offs_kernel<<<1, 1>>>();
    moe_gemm_tf32<D_DIM, 0><<<dim3(N1 / 128, MT_MAX), 128, DSMEM_SZ>>>(nullptr);   // 4th: ncu slot
    silu_kernel<<<(MAX_ROWS * (F_DIM / 4) + 255) / 256, 256>>>();
    moe_gemm_tf32<F_DIM, 1><<<dim3(D_DIM / 128, MT_MAX), 128, DSMEM_SZ>>>(nullptr);
    combine_kernel<<<(T_TOK * D_DIM / 4 + 255) / 256, 256>>>(out);
}

// round 16
// speedup vs baseline: 1.0804x; 1.0328x over previous
#include <cuda_runtime.h>
#include <cuda_bf16.h>
#include <math.h>
#include <stdint.h>

#define T_TOK 8192
#define D_DIM 2048
#define F_DIM 3584
#define E_NUM 8
#define N1 (2 * F_DIM)          // 7168
#define MT_MAX 136
#define MAX_ROWS (MT_MAX * 128)

#define W2E ((size_t)E_NUM * D_DIM * F_DIM)
#define XE  ((size_t)T_TOK * D_DIM)

#define GATE_BLKS (T_TOK / 8)                    // 1024 blocks, warp/token, 256 thr
#define CVT_QUADS ((W2E + XE) / 4)
#define CVT_BLKS  ((unsigned)((CVT_QUADS + 255) / 256))

// ---------------- scratch ----------------
__device__ float g_h[(size_t)MAX_ROWS * N1];     // gemm1 out; later reused as Y (gemm2 out)
__device__ float g_act[(size_t)MAX_ROWS * F_DIM];
__device__ float g_w2r[W2E];
__device__ float g_xr[XE];
__device__ int   g_tok[E_NUM * T_TOK];
__device__ int   g_slot[2 * T_TOK];              // per token: (e<<13)|p
__device__ float g_wt[2 * T_TOK];
__device__ int   g_cnt[E_NUM];
__device__ int   g_ts[E_NUM + 1];

// ---------------- helpers ----------------
__device__ __forceinline__ uint32_t smem_u32(const void* p) {
    uint32_t a;
    asm("{ .reg .u64 t; cvta.to.shared.u64 t, %1; cvt.u32.u64 %0, t; }" : "=r"(a) : "l"(p));
    return a;
}
__device__ __forceinline__ float tf32r(float v) {
    uint32_t r;
    asm("cvt.rna.tf32.f32 %0, %1;" : "=r"(r) : "f"(v));
    return __uint_as_float(r);
}
#define CP_ASYNC16(dst, src, sz) \
    asm volatile("cp.async.cg.shared.global [%0], [%1], 16, %2;" :: "r"(dst), "l"(src), "r"(sz) : "memory")
#define CP_COMMIT() asm volatile("cp.async.commit_group;" ::: "memory")
#define CP_WAIT(n)  asm volatile("cp.async.wait_group %0;" :: "n"(n) : "memory")

// padded + chunk-permuted row: stride 144B; 16B-chunk kc stored at (kc + 2*row)&7
#define RPB 144
#define TILE_T (128 * RPB)        // 18432 B (A or B tile: 128 rows x 32 K)
#define STAGE  (2 * TILE_T)       // 36864 B
#define NSTG   3
#define DSMEM_SZ (NSTG * STAGE + 1024)

__device__ __forceinline__ uint32_t taddr(uint32_t base, int row, int col) {
    int pc = ((col >> 2) + 2 * row) & 7;
    return base + row * RPB + pc * 16 + (col & 3) * 4;
}
__device__ __forceinline__ uint32_t lds_raw(uint32_t a) {
    uint32_t v;
    asm volatile("ld.shared.b32 %0, [%1];" : "=r"(v) : "r"(a));
    return v;
}
#define MMA_TF32(c, a, b0, b1)                                                      \
    asm volatile("mma.sync.aligned.m16n8k8.row.col.f32.tf32.tf32.f32 "              \
        "{%0,%1,%2,%3}, {%4,%5,%6,%7}, {%8,%9}, {%0,%1,%2,%3};"                     \
        : "+f"((c)[0]), "+f"((c)[1]), "+f"((c)[2]), "+f"((c)[3])                    \
        : "r"((a)[0]), "r"((a)[1]), "r"((a)[2]), "r"((a)[3]), "r"(b0), "r"(b1))

// ---------------- init ----------------
__global__ void init_kernel() { if (threadIdx.x < E_NUM) g_cnt[threadIdx.x] = 0; }

// ---------------- fused gate + tf32 rounding pre-pass (w2 + x only; wv1 fed raw) ----------------
__global__ void fused_pre_kernel(const float* __restrict__ x,
                                 const float* __restrict__ gw,
                                 const float* __restrict__ w2) {
    if (blockIdx.x < GATE_BLKS) {
        int warp = (blockIdx.x * blockDim.x + threadIdx.x) >> 5;
        int lane = threadIdx.x & 31;
        const float* xr = x + (size_t)warp * D_DIM;
        float acc[E_NUM];
#pragma unroll
        for (int e = 0; e < E_NUM; e++) acc[e] = 0.f;
        for (int d = lane; d < D_DIM; d += 32) {
            float xv = xr[d];
#pragma unroll
            for (int e = 0; e < E_NUM; e++) acc[e] += xv * gw[e * D_DIM + d];
        }
#pragma unroll
        for (int e = 0; e < E_NUM; e++)
#pragma unroll
            for (int o = 16; o > 0; o >>= 1) acc[e] += __shfl_xor_sync(0xFFFFFFFFu, acc[e], o);
        if (lane == 0) {
            int i1 = 0; float l1 = acc[0];
#pragma unroll
            for (int e = 1; e < E_NUM; e++) if (acc[e] > l1) { l1 = acc[e]; i1 = e; }
            int i2 = -1; float l2 = -3.4e38f;
#pragma unroll
            for (int e = 0; e < E_NUM; e++) if (e != i1 && acc[e] > l2) { l2 = acc[e]; i2 = e; }
            float w1 = 1.f / (1.f + expf(l2 - l1));
            float w2v = 1.f - w1;
            int p1 = atomicAdd(&g_cnt[i1], 1);
            g_tok[i1 * T_TOK + p1] = warp;
            g_slot[2 * warp] = (i1 << 13) | p1; g_wt[2 * warp] = w1;
            int p2 = atomicAdd(&g_cnt[i2], 1);
            g_tok[i2 * T_TOK + p2] = warp;
            g_slot[2 * warp + 1] = (i2 << 13) | p2; g_wt[2 * warp + 1] = w2v;
        }
        return;
    }
    const size_t W2Q = W2E / 4, XQ = XE / 4;
    size_t i = (size_t)(blockIdx.x - GATE_BLKS) * blockDim.x + threadIdx.x;
    const float4* src;
    float4* dst;
    if (i < W2Q) {
        src = (const float4*)w2 + i;       dst = (float4*)g_w2r + i;
    } else if (i < W2Q + XQ) {
        src = (const float4*)x + (i - W2Q); dst = (float4*)g_xr + (i - W2Q);
    } else return;
    float4 v = *src;
    v.x = tf32r(v.x); v.y = tf32r(v.y); v.z = tf32r(v.z); v.w = tf32r(v.w);
    *dst = v;
}

__global__ void offs_kernel() {
    int t = 0;
    for (int e = 0; e < E_NUM; e++) { g_ts[e] = t; t += (g_cnt[e] + 127) >> 7; }
    g_ts[E_NUM] = t;
}

// flat silu: one float4 per thread over all padded rows (garbage rows are
// row-isolated and never stored downstream: gemm2 epilogue guards on s_tok).
__global__ void silu_kernel() {
    const int F4 = F_DIM / 4;
    int idx = blockIdx.x * blockDim.x + threadIdx.x;
    int row = idx / F4;
    if (row >= g_ts[E_NUM] * 128) return;
    int c4 = idx % F4;
    const float4* gp = (const float4*)(g_h + (size_t)row * N1) + c4;
    float4 g = gp[0];
    float4 u = gp[F_DIM / 4];
    float4 o;
    o.x = tf32r((g.x / (1.f + expf(-g.x))) * u.x);
    o.y = tf32r((g.y / (1.f + expf(-g.y))) * u.y);
    o.z = tf32r((g.z / (1.f + expf(-g.z))) * u.z);
    o.w = tf32r((g.w / (1.f + expf(-g.w))) * u.w);
    ((float4*)(g_act + (size_t)row * F_DIM))[c4] = o;
}

// final: out[t] = w1*Y[r1] + w2*Y[r2]
__global__ void combine_kernel(float* __restrict__ out) {
    const int C4 = D_DIM / 4;
    int idx = blockIdx.x * blockDim.x + threadIdx.x;
    if (idx >= T_TOK * C4) return;
    int t = idx / C4, c = idx % C4;
    int s1 = g_slot[2 * t], s2 = g_slot[2 * t + 1];
    float w1 = g_wt[2 * t], w2 = g_wt[2 * t + 1];
    int r1 = g_ts[s1 >> 13] * 128 + (s1 & 8191);
    int r2 = g_ts[s2 >> 13] * 128 + (s2 & 8191);
    float4 y1 = *((const float4*)g_h + (size_t)r1 * C4 + c);
    float4 y2 = *((const float4*)g_h + (size_t)r2 * C4 + c);
    float4 o;
    o.x = w1 * y1.x + w2 * y2.x;
    o.y = w1 * y1.y + w2 * y2.y;
    o.z = w1 * y1.z + w2 * y2.z;
    o.w = w1 * y1.w + w2 * y2.w;
    ((float4*)out)[idx] = o;
}

// ---------------- TF32 GEMM: CTA 128M x 128N, 4 warps (64x64), 3-stage, 2 CTA/SM ----------------
// MODE 0: A = g_xr gathered, B = RAW wv1 (arg)  -> g_h[.,N1]       (K=2048, N=7168)
// MODE 1: A = g_act,         B = g_w2r (rounded) -> Y=g_h[.,D_DIM]  (K=3584, N=2048)
template <int KTOT, int MODE>
__device__ __forceinline__ void load_stage(uint32_t Ab, uint32_t Bb,
                                           const float* __restrict__ W,
                                           const int* s_tok, int mt, int k0, int tid) {
#pragma unroll
    for (int i = 0; i < 16; i++) {
        int id = tid + 128 * i;
        if (id < 1024) {                      // A: 128 rows x 8 chunks
            int r = id >> 3, kc = id & 7;
            int pc = (kc + 2 * r) & 7;
            uint32_t ad = Ab + r * RPB + pc * 16;
            if (MODE == 0) {
                int tok = s_tok[r];
                const float* src = g_xr + (size_t)(tok < 0 ? 0 : tok) * KTOT + k0 + kc * 4;
                int sz = (tok >= 0) ? 16 : 0;
                CP_ASYNC16(ad, src, sz);
            } else {
                const float* src = g_act + (size_t)(mt * 128 + r) * KTOT + k0 + kc * 4;
                CP_ASYNC16(ad, src, 16);
            }
        } else {                              // B: 128 rows x 8 chunks
            int ib = id - 1024;
            int r = ib >> 3, kc = ib & 7;
            int pc = (kc + 2 * r) & 7;
            uint32_t bd = Bb + r * RPB + pc * 16;
            const float* bs = W + (size_t)r * KTOT + k0 + kc * 4;
            CP_ASYNC16(bd, bs, 16);
        }
    }
}

__device__ __forceinline__ void load_frags(uint32_t At, uint32_t Bt, int kb,
                                           int m0w, int n0w, int grp, int qid,
                                           uint32_t a[4][4], uint32_t b[8][2]) {
#pragma unroll
    for (int mf = 0; mf < 4; mf++) {
        int row = m0w + mf * 16 + grp;
        a[mf][0] = lds_raw(taddr(At, row,     kb + qid));
        a[mf][1] = lds_raw(taddr(At, row + 8, kb + qid));
        a[mf][2] = lds_raw(taddr(At, row,     kb + qid + 4));
        a[mf][3] = lds_raw(taddr(At, row + 8, kb + qid + 4));
    }
#pragma unroll
    for (int nb = 0; nb < 8; nb++) {
        int n = n0w + nb * 8 + grp;
        b[nb][0] = lds_raw(taddr(Bt, n, kb + qid));
        b[nb][1] = lds_raw(taddr(Bt, n, kb + qid + 4));
    }
}

template <int KTOT, int MODE>
__global__ void __launch_bounds__(128, 2) moe_gemm_tf32(float* __restrict__ Outp,
                                                        const float* __restrict__ Wraw) {
    const int mt = blockIdx.y;
    int ts[E_NUM + 1];
#pragma unroll
    for (int i = 0; i <= E_NUM; i++) ts[i] = g_ts[i];
    if (mt >= ts[E_NUM]) return;
    int e = 0;
#pragma unroll
    for (int i = 0; i < E_NUM; i++) if (mt >= ts[i + 1]) e = i + 1;
    const int cnt = g_cnt[e];
    const int mloc0 = (mt - ts[e]) * 128;
    const int n0 = blockIdx.x * 128;
    const int NTOT = gridDim.x * 128;
    const float* __restrict__ Wbase = (MODE == 0) ? Wraw : g_w2r;
    const float* __restrict__ W = Wbase + ((size_t)e * NTOT + n0) * KTOT;

    extern __shared__ __align__(16) char smem[];
    const uint32_t tb = smem_u32(smem);
    int* s_tok = (int*)(smem + NSTG * STAGE);

    const int tid  = threadIdx.x;
    const int wid  = tid >> 5;
    const int lane = tid & 31;
    const int grp  = lane >> 2;
    const int qid  = lane & 3;

    {
        int ml = mloc0 + tid;
        s_tok[tid] = (ml < cnt) ? g_tok[e * T_TOK + ml] : -1;
    }
    __syncthreads();

    uint32_t Ab[NSTG], Bb[NSTG];
#pragma unroll
    for (int i = 0; i < NSTG; i++) { Ab[i] = tb + i * STAGE; Bb[i] = Ab[i] + TILE_T; }

    // warp tile 64(M) x 64(N)
    const int m0w = (wid & 1) * 64;
    const int n0w = (wid >> 1) * 64;

    float c[4][8][4];
#pragma unroll
    for (int i = 0; i < 4; i++)
#pragma unroll
        for (int j = 0; j < 8; j++)
#pragma unroll
            for (int k = 0; k < 4; k++) c[i][j][k] = 0.f;

    constexpr int NST = KTOT / 32;
    load_stage<KTOT, MODE>(Ab[0], Bb[0], W, s_tok, mt, 0, tid);
    CP_COMMIT();
    load_stage<KTOT, MODE>(Ab[1], Bb[1], W, s_tok, mt, 32, tid);
    CP_COMMIT();

    uint32_t a[2][4][4], b[2][8][2];   // ks-level double-buffered fragments

    int sc = 0;                 // stage being consumed
    int sl = 2;                 // stage to load next
    for (int kt = 0; kt < NST; kt++) {
        if (kt == NST - 1) { CP_WAIT(0); } else { CP_WAIT(1); }
        __syncthreads();        // stage sc visible; all warps done with stage sl (consumed at kt-1)

        if (kt + 2 < NST) {
            load_stage<KTOT, MODE>(Ab[sl], Bb[sl], W, s_tok, mt, (kt + 2) * 32, tid);
            CP_COMMIT();
        }

        const uint32_t At = Ab[sc], Bt = Bb[sc];
        load_frags(At, Bt, 0, m0w, n0w, grp, qid, a[0], b[0]);
#pragma unroll
        for (int ks = 0; ks < 4; ks++) {
            const int cur = ks & 1;
            if (ks < 3)
                load_frags(At, Bt, (ks + 1) * 8, m0w, n0w, grp, qid, a[cur ^ 1], b[cur ^ 1]);
#pragma unroll
            for (int nb = 0; nb < 8; nb++) {
#pragma unroll
                for (int mf = 0; mf < 4; mf++)
                    MMA_TF32(c[mf][nb], a[cur][mf], b[cur][nb][0], b[cur][nb][1]);
            }
        }
        sc = (sc + 1 == NSTG) ? 0 : sc + 1;
        sl = (sl + 1 == NSTG) ? 0 : sl + 1;
    }

    // ---- epilogue ----
#pragma unroll
    for (int mf = 0; mf < 4; mf++) {
#pragma unroll
        for (int half = 0; half < 2; half++) {
            int row = m0w + mf * 16 + half * 8 + grp;
            if (MODE == 0) {
                if (mloc0 + row < cnt) {
                    float* op = g_h + (size_t)(mt * 128 + row) * N1 + n0 + n0w + qid * 2;
#pragma unroll
                    for (int nb = 0; nb < 8; nb++)
                        *(float2*)(op + nb * 8) = make_float2(c[mf][nb][half * 2],
                                                              c[mf][nb][half * 2 + 1]);
                }
            } else {
                if (s_tok[row] >= 0) {
                    float* op = g_h + (size_t)(mt * 128 + row) * D_DIM + n0 + n0w + qid * 2;
#pragma unroll
                    for (int nb = 0; nb < 8; nb++)
                        *(float2*)(op + nb * 8) = make_float2(c[mf][nb][half * 2],
                                                              c[mf][nb][half * 2 + 1]);
                }
            }
        }
    }
}

// ---------------- host ----------------
extern "C" void kernel_launch(void* const* d_in, const int* in_sizes, int n_in,
                              void* d_out, int out_size) {
    const float* x   = (const float*)d_in[0];
    const float* gw  = (const float*)d_in[1];
    const float* wv1 = (const float*)d_in[2];
    const float* w2  = (const float*)d_in[3];
    float* out = (float*)d_out;

    cudaFuncSetAttribute(moe_gemm_tf32<D_DIM, 0>, cudaFuncAttributeMaxDynamicSharedMemorySize, DSMEM_SZ);
    cudaFuncSetAttribute(moe_gemm_tf32<F_DIM, 1>, cudaFuncAttributeMaxDynamicSharedMemorySize, DSMEM_SZ);

    init_kernel<<<1, 32>>>();
    fused_pre_kernel<<<GATE_BLKS + CVT_BLKS, 256>>>(x, gw, w2);
    offs_kernel<<<1, 1>>>();
    moe_gemm_tf32<D_DIM, 0><<<dim3(N1 / 128, MT_MAX), 128, DSMEM_SZ>>>(nullptr, wv1);  // 4th: ncu slot
    silu_kernel<<<(MAX_ROWS * (F_DIM / 4) + 255) / 256, 256>>>();
    moe_gemm_tf32<F_DIM, 1><<<dim3(D_DIM / 128, MT_MAX), 128, DSMEM_SZ>>>(nullptr, nullptr);
    combine_kernel<<<(T_TOK * D_DIM / 4 + 255) / 256, 256>>>(out);
}